// round 17
// baseline (speedup 1.0000x reference)
#include <cuda_runtime.h>
#include <math.h>
#include <float.h>

#define BB 64
#define CC 100
#define KK 5
#define NN (BB*CC*KK)      // 32000
#define NBINS 1024
#define NAB 10             // Phase-A blocks: 10 x 32 warps = 320 = BB*KK exactly
#define NGB 11             // Gram blocks (2640 tiles * 4 threads / 1024)
#define NBLK (NAB+NGB)     // 21
#define NTHR 1024
#define DMINF (-8.0f)
#define INVWF 64.0f        // NBINS / 16; symmetric range => binOf(-d) == 1023 - binOf(d)

#define NTILES (KK*528)    // 2640: B x B upper-tri 2x2 tiles (32*33/2 per k)

// ---------------- device scratch (no allocs allowed) ----------------
__device__ float2 g_hist2[NBINS];      // (sumT, sumS) merged from block-private hists
__device__ float  g_tk[KK*BB*CC], g_sk[KK*BB*CC];   // [k][b][c]
__device__ double g_tt, g_ss, g_ts, g_kl[KK], g_ce, g_sub;
__device__ unsigned g_tkdone;          // tk/sk stores complete
__device__ unsigned g_adone;           // full Phase-A complete (hist + scalars merged)
__device__ unsigned g_gdone;           // Gram blocks complete

__device__ __forceinline__ int binOf(float x){
    int j = (int)floorf((x - DMINF) * INVWF);
    return min(max(j, 0), NBINS-1);
}

__device__ __forceinline__ float blockSum(float v, float* shR){
    int lane = threadIdx.x & 31, w = threadIdx.x >> 5;
    #pragma unroll
    for (int o=16;o;o>>=1) v += __shfl_down_sync(0xffffffffu, v, o);
    if (lane==0) shR[w] = v;
    __syncthreads();
    float r = 0.f;
    if (threadIdx.x==0){
        #pragma unroll
        for (int i=0;i<NTHR/32;i++) r += shR[i];
    }
    __syncthreads();
    return r;   // valid on tid 0 only
}

__global__ void __launch_bounds__(NTHR)
fused_kernel(const float* __restrict__ ls, const float* __restrict__ lt,
             const int* __restrict__ tgt, float* __restrict__ out)
{
    __shared__ float4 shT[NBINS];          // 16 KB: block0 scan table; low 8 KB = A private hist
    __shared__ float  shA[NTHR], shB[NTHR];
    __shared__ float  shR[NTHR/32];
    __shared__ float  shKL[KK], shTT, shSS, shTS;

    const int tid  = threadIdx.x;
    const int bid  = blockIdx.x;
    const int lane = tid & 31;
    const int wid  = tid >> 5;

    if (bid < NAB){
        // ============ Phase A: softmax + KD + L2 dots + private smem hist ============
        // issue input loads FIRST so DRAM latency overlaps smem init
        int gw = bid*32 + wid;             // 0..319, exactly BB*KK tasks
        int b = gw / KK, k = gw % KK;
        float invT = 1.0f / (float)(k+1);
        float av[4], bv[4];
        #pragma unroll
        for (int q=0;q<4;q++){
            int c = lane + 32*q;
            bool ok = c < CC;
            av[q] = ok ? ls[b*CC+c] : 0.f;
            bv[q] = ok ? lt[b*CC+c] : 0.f;
        }
        int tg = (k==0) ? tgt[b] : -1;

        float2* shH = (float2*)shT;        // 1024-bin private histogram (8 KB)
        shH[tid] = make_float2(0.f, 0.f);  // 1024 threads cover all bins
        if (tid < KK) shKL[tid] = 0.f;
        if (tid == KK)   shTT = 0.f;
        if (tid == KK+1) shSS = 0.f;
        if (tid == KK+2) shTS = 0.f;
        __syncthreads();

        float amax = -FLT_MAX, bmax = -FLT_MAX;
        #pragma unroll
        for (int q=0;q<4;q++){
            int c = lane + 32*q;
            av[q] = (c<CC) ? av[q]*invT : -FLT_MAX;
            bv[q] = (c<CC) ? bv[q]*invT : -FLT_MAX;
            amax = fmaxf(amax, av[q]);
            bmax = fmaxf(bmax, bv[q]);
        }
        #pragma unroll
        for (int o=16;o;o>>=1){
            amax = fmaxf(amax, __shfl_xor_sync(0xffffffffu, amax, o));
            bmax = fmaxf(bmax, __shfl_xor_sync(0xffffffffu, bmax, o));
        }
        float ea[4], eb[4], sumA = 0.f, sumB = 0.f;
        #pragma unroll
        for (int q=0;q<4;q++){
            int c = lane + 32*q;
            ea[q] = (c<CC) ? __expf(av[q]-amax) : 0.f;
            eb[q] = (c<CC) ? __expf(bv[q]-bmax) : 0.f;
            sumA += ea[q]; sumB += eb[q];
        }
        #pragma unroll
        for (int o=16;o;o>>=1){
            sumA += __shfl_xor_sync(0xffffffffu, sumA, o);
            sumB += __shfl_xor_sync(0xffffffffu, sumB, o);
        }
        float lA = __logf(sumA), lB = __logf(sumB);
        float rA = 1.f/sumA, rB = 1.f/sumB;
        float kl=0.f, tt=0.f, ssv=0.f, tsv=0.f;
        #pragma unroll
        for (int q=0;q<4;q++){
            int c = lane + 32*q;
            if (c < CC){
                float lq = av[q]-amax-lA;
                float lp = bv[q]-bmax-lB;
                float sv = ea[q]*rA;
                float tv = eb[q]*rB;
                float dv = lp - lq;
                int i2 = (k*BB + b)*CC + c;
                g_tk[i2]=tv; g_sk[i2]=sv;
                int j = binOf(dv);
                atomicAdd(&shH[j].x, tv);
                atomicAdd(&shH[j].y, sv);
                kl  += tv*dv;
                tt  += tv*tv;
                ssv += sv*sv;
                tsv += tv*sv;
                if (c == tg) atomicAdd(&g_ce, (double)(-lq));
            }
        }
        #pragma unroll
        for (int o=16;o;o>>=1){
            kl  += __shfl_xor_sync(0xffffffffu, kl,  o);
            tt  += __shfl_xor_sync(0xffffffffu, tt,  o);
            ssv += __shfl_xor_sync(0xffffffffu, ssv, o);
            tsv += __shfl_xor_sync(0xffffffffu, tsv, o);
        }
        if (lane==0){
            atomicAdd(&shKL[k], kl);
            atomicAdd(&shTT, tt);
            atomicAdd(&shSS, ssv);
            atomicAdd(&shTS, tsv);
        }
        __threadfence();                    // tk/sk stores visible
        __syncthreads();
        if (tid==0) atomicAdd(&g_tkdone, 1u);   // early release for Gram blocks

        // merge private hist -> global: ONE bin per thread (skip empty)
        {
            float2 h = shH[tid];
            if (h.x != 0.f || h.y != 0.f){
                atomicAdd(&g_hist2[tid].x, h.x);
                atomicAdd(&g_hist2[tid].y, h.y);
            }
        }
        if (tid < KK)     atomicAdd(&g_kl[tid], (double)shKL[tid]);
        if (tid == KK)    atomicAdd(&g_tt, (double)shTT);
        if (tid == KK+1)  atomicAdd(&g_ss, (double)shSS);
        if (tid == KK+2)  atomicAdd(&g_ts, (double)shTS);
        __threadfence();
        __syncthreads();
        if (tid==0) atomicAdd(&g_adone, 1u);

        if (bid == 0){
            // ============ Block 0: bin-space L1 + final combine ============
            if (tid == 0){
                while (*(volatile unsigned*)&g_adone != NAB) { }
            }
            __threadfence();
            __syncthreads();

            // load merged hist: 1 bin/thread; inclusive scan over 1024 entries
            float2 h = g_hist2[tid];
            float bt = h.x, bs = h.y;
            shA[tid] = bt; shB[tid] = bs;
            __syncthreads();
            #pragma unroll
            for (int off=1; off<NTHR; off<<=1){
                float vT=shA[tid], vS=shB[tid];
                float uT=0.f,uS=0.f;
                if (tid>=off){ uT=shA[tid-off]; uS=shB[tid-off]; }
                __syncthreads();
                shA[tid]=vT+uT; shB[tid]=vS+uS;
                __syncthreads();
            }
            float Ttot = shA[NTHR-1], Stot = shB[NTHR-1];
            shT[tid] = make_float4(shA[tid], shB[tid], bt, bs);  // (inclT, inclS, binT, binS)
            __syncthreads();

            // L1 in bin space: elements of bin j see mirror bin 1023-j
            float4 bp = shT[(NBINS-1) - tid];
            float pt = Ttot - bp.x + 0.5f*bp.z;
            float ps = Stot - bp.y + 0.5f*bp.w;
            float contrib = bt*(2.f*pt - Ttot) - bs*(2.f*ps - Stot);
            float l1f = blockSum(contrib, shR);

            if (tid == 0){
                while (*(volatile unsigned*)&g_gdone != NGB) { }
            }
            __threadfence();
            __syncthreads();
            if (tid == 0){
                double ce = g_ce / (double)BB;
                double kd = 0.0;
                #pragma unroll
                for (int k2=0;k2<KK;k2++){
                    double T = (double)(k2+1);
                    kd += (g_kl[k2] / (double)(BB*CC)) * (0.7*T*T) + ce * 0.3;
                }
                double tt2=g_tt, ss2=g_ss, ts2=g_ts;
                double l2 = 0.00025*(tt2*tt2 - 2.0*ts2*ts2 + ss2*ss2);
                out[0] = (float)(kd + 0.00025*(double)l1f + l2 + g_sub);
                g_tt = 0.0; g_ss = 0.0; g_ts = 0.0;
                g_ce = 0.0; g_sub = 0.0;
                #pragma unroll
                for (int k2=0;k2<KK;k2++) g_kl[k2] = 0.0;
                g_tkdone = 0u; g_adone = 0u; g_gdone = 0u;
            }
            g_hist2[tid] = make_float2(0.f, 0.f);   // 1 store/thread cleanup
        }
    } else {
        // ====== Gram blocks: B x B tiles only, 4 threads per tile (quarter C-ranges) ======
        // M1 = T T^T, M2 = T S^T, M3 = S S^T  (64x64 each, per k)
        // loss_sub1 = sum ||M1-M3||_F^2
        // loss_sub2 = sum ||M1||^2 - 2||M2||^2 + ||M3||^2   (trace identity for C x C Gram)
        if (tid == 0){
            while (*(volatile unsigned*)&g_tkdone != NAB) { }
        }
        __threadfence();
        __syncthreads();

        int gid  = (bid-NAB)*NTHR + tid;
        int pair = gid >> 2;               // tile index
        int quar = gid & 3;                // quarter of the C contraction
        float m1[4]={0.f,0.f,0.f,0.f}, m3[4]={0.f,0.f,0.f,0.f};
        float m2f[4]={0.f,0.f,0.f,0.f}, m2b[4]={0.f,0.f,0.f,0.f};
        float w = 0.f;
        int isdiag = 0;
        if (pair < NTILES){
            int k = pair / 528;
            int p = pair - k*528;
            int a = 0;
            while (p >= 32-a){ p -= 32-a; a++; }
            int b2 = a + p;
            int i0 = 2*a, j0 = 2*b2;
            const float* T = g_tk + k*BB*CC;
            const float* S = g_sk + k*BB*CC;
            const int lo[5] = {0, 28, 52, 76, 100};
            int c4lo = lo[quar], c4hi = lo[quar+1];
            for (int c4=c4lo;c4<c4hi;c4+=4){
                float4 Ti0=*(const float4*)(T+ i0   *CC+c4);
                float4 Ti1=*(const float4*)(T+(i0+1)*CC+c4);
                float4 Tj0=*(const float4*)(T+ j0   *CC+c4);
                float4 Tj1=*(const float4*)(T+(j0+1)*CC+c4);
                float4 Si0=*(const float4*)(S+ i0   *CC+c4);
                float4 Si1=*(const float4*)(S+(i0+1)*CC+c4);
                float4 Sj0=*(const float4*)(S+ j0   *CC+c4);
                float4 Sj1=*(const float4*)(S+(j0+1)*CC+c4);
                m1[0] += Ti0.x*Tj0.x + Ti0.y*Tj0.y + Ti0.z*Tj0.z + Ti0.w*Tj0.w;
                m1[1] += Ti0.x*Tj1.x + Ti0.y*Tj1.y + Ti0.z*Tj1.z + Ti0.w*Tj1.w;
                m1[2] += Ti1.x*Tj0.x + Ti1.y*Tj0.y + Ti1.z*Tj0.z + Ti1.w*Tj0.w;
                m1[3] += Ti1.x*Tj1.x + Ti1.y*Tj1.y + Ti1.z*Tj1.z + Ti1.w*Tj1.w;
                m3[0] += Si0.x*Sj0.x + Si0.y*Sj0.y + Si0.z*Sj0.z + Si0.w*Sj0.w;
                m3[1] += Si0.x*Sj1.x + Si0.y*Sj1.y + Si0.z*Sj1.z + Si0.w*Sj1.w;
                m3[2] += Si1.x*Sj0.x + Si1.y*Sj0.y + Si1.z*Sj0.z + Si1.w*Sj0.w;
                m3[3] += Si1.x*Sj1.x + Si1.y*Sj1.y + Si1.z*Sj1.z + Si1.w*Sj1.w;
                m2f[0] += Ti0.x*Sj0.x + Ti0.y*Sj0.y + Ti0.z*Sj0.z + Ti0.w*Sj0.w;
                m2f[1] += Ti0.x*Sj1.x + Ti0.y*Sj1.y + Ti0.z*Sj1.z + Ti0.w*Sj1.w;
                m2f[2] += Ti1.x*Sj0.x + Ti1.y*Sj0.y + Ti1.z*Sj0.z + Ti1.w*Sj0.w;
                m2f[3] += Ti1.x*Sj1.x + Ti1.y*Sj1.y + Ti1.z*Sj1.z + Ti1.w*Sj1.w;
                m2b[0] += Tj0.x*Si0.x + Tj0.y*Si0.y + Tj0.z*Si0.z + Tj0.w*Si0.w;
                m2b[1] += Tj1.x*Si0.x + Tj1.y*Si0.y + Tj1.z*Si0.z + Tj1.w*Si0.w;
                m2b[2] += Tj0.x*Si1.x + Tj0.y*Si1.y + Tj0.z*Si1.z + Tj0.w*Si1.w;
                m2b[3] += Tj1.x*Si1.x + Tj1.y*Si1.y + Tj1.z*Si1.z + Tj1.w*Si1.w;
            }
            w = (a==b2) ? 1.f : 2.f;
            isdiag = (a==b2);
        }
        // combine quarters (4 consecutive lanes of the same warp)
        #pragma unroll
        for (int m=0;m<4;m++){
            m1[m]  += __shfl_xor_sync(0xffffffffu, m1[m],  1);
            m1[m]  += __shfl_xor_sync(0xffffffffu, m1[m],  2);
            m3[m]  += __shfl_xor_sync(0xffffffffu, m3[m],  1);
            m3[m]  += __shfl_xor_sync(0xffffffffu, m3[m],  2);
            m2f[m] += __shfl_xor_sync(0xffffffffu, m2f[m], 1);
            m2f[m] += __shfl_xor_sync(0xffffffffu, m2f[m], 2);
            m2b[m] += __shfl_xor_sync(0xffffffffu, m2b[m], 1);
            m2b[m] += __shfl_xor_sync(0xffffffffu, m2b[m], 2);
        }
        float val = 0.f;
        if (quar==0 && w > 0.f){
            float s1=0.f, sm1=0.f, sm3=0.f, s2f=0.f, s2b=0.f;
            #pragma unroll
            for (int m=0;m<4;m++){
                float dG = m1[m]-m3[m];
                s1  += dG*dG;
                sm1 += m1[m]*m1[m];
                sm3 += m3[m]*m3[m];
                s2f += m2f[m]*m2f[m];
                s2b += m2b[m]*m2b[m];
            }
            val = w*(s1 + sm1 + sm3) - 2.f*(isdiag ? s2f : (s2f + s2b));
        }
        float r2s = blockSum(val, shR);
        if (tid==0){
            atomicAdd(&g_sub, (double)r2s);
            __threadfence();
            atomicAdd(&g_gdone, 1u);
        }
    }
}

// ---------------- launch ----------------
extern "C" void kernel_launch(void* const* d_in, const int* in_sizes, int n_in,
                              void* d_out, int out_size){
    (void)in_sizes; (void)n_in; (void)out_size;
    const float* ls  = (const float*)d_in[0];  // logits_student [64,100]
    const float* lt  = (const float*)d_in[1];  // logits_teacher [64,100]
    const int*   tgt = (const int*)  d_in[2];  // target [64]
    float* out = (float*)d_out;

    fused_kernel<<<NBLK, NTHR>>>(ls, lt, tgt, out);
}